// round 3
// baseline (speedup 1.0000x reference)
#include <cuda_runtime.h>
#include <cuda_bf16.h>

#define NODES 50000
#define NEDGES 800000
#define F 128

// ---------------- scratch (device globals; no runtime allocation) ------------
__device__ float g_deg[NODES];          // in-degree, then inv_deg (in place)
__device__ float g_agg[NODES * F];      // scatter accumulator (reused both layers)
__device__ float g_h1[NODES * F];
__device__ float g_h2[NODES * F];
__device__ int   g_is64;                // 1 if edge_index is int64, 0 if int32

// ---------------- index dtype detection --------------------------------------
// int64 little-endian with values < 50000 => every odd 32-bit word is 0.
// int32 random ids in [0,50000) => odd words are ~never all zero (p ~ 2^-4000).
__global__ void detect_kernel(const int* __restrict__ p) {
    __shared__ int ok;
    if (threadIdx.x == 0) ok = 1;
    __syncthreads();
    if (p[2 * threadIdx.x + 1] != 0) atomicAnd(&ok, 0);
    __syncthreads();
    if (threadIdx.x == 0) g_is64 = ok;
}

__device__ __forceinline__ int load_idx(const void* __restrict__ p, long i, int is64) {
    if (is64) return (int)((const long long*)p)[i];
    return ((const int*)p)[i];
}

// ---------------- zero fill --------------------------------------------------
__global__ void zero_kernel(float* __restrict__ p, int n4) {
    int i = blockIdx.x * blockDim.x + threadIdx.x;
    float4 z = make_float4(0.f, 0.f, 0.f, 0.f);
    for (; i < n4; i += gridDim.x * blockDim.x)
        ((float4*)p)[i] = z;
}

// ---------------- degree -----------------------------------------------------
__global__ void deg_kernel(const void* __restrict__ ei, float* __restrict__ deg, int nE) {
    int i = blockIdx.x * blockDim.x + threadIdx.x;
    int is64 = g_is64;
    if (i < nE) {
        int d = load_idx(ei, (long)nE + i, is64);   // dst row
        if (d >= 0 && d < NODES) atomicAdd(&deg[d], 1.0f);
    }
}

__global__ void invdeg_kernel(float* __restrict__ deg, int n) {
    int i = blockIdx.x * blockDim.x + threadIdx.x;
    if (i < n) deg[i] = 1.0f / fmaxf(deg[i], 1.0f);
}

// ---------------- scatter: agg[dst] += feat[src] -----------------------------
// one warp per edge; float4 gather + vector red.global (sm_90+)
__global__ __launch_bounds__(256) void scatter_kernel(
    const void* __restrict__ ei,
    const float* __restrict__ feat, float* __restrict__ agg, int nE)
{
    int w = (blockIdx.x * blockDim.x + threadIdx.x) >> 5;
    int lane = threadIdx.x & 31;
    if (w >= nE) return;
    int is64 = g_is64;
    int s = load_idx(ei, w, is64);
    int d = load_idx(ei, (long)nE + w, is64);
    if ((unsigned)s >= NODES || (unsigned)d >= NODES) return;
    float4 v = ((const float4*)(feat + (long)s * F))[lane];
    float* p = agg + (long)d * F + lane * 4;
    asm volatile("red.global.add.v4.f32 [%0], {%1,%2,%3,%4};"
                 :: "l"(p), "f"(v.x), "f"(v.y), "f"(v.z), "f"(v.w) : "memory");
}

// ---------------- fused SAGE layer: out = relu(agg*inv @ Wl + root @ Wr + b) -
// block: 256 thr (8 warps), 64 rows/block (8 rows/warp), lane covers 4 cols.
__global__ __launch_bounds__(256) void sage_gemm_kernel(
    const float* __restrict__ agg, const float* __restrict__ root,
    const float* __restrict__ invdeg,
    const float* __restrict__ Wl, const float* __restrict__ Wr,
    const float* __restrict__ bias, float* __restrict__ out, int n)
{
    __shared__ float sWl[32][F];
    __shared__ float sWr[32][F];
    __shared__ float rta[8][8][32];
    __shared__ float rtx[8][8][32];

    int tid  = threadIdx.x;
    int w    = tid >> 5;
    int lane = tid & 31;
    int rowBase = blockIdx.x * 64 + w * 8;

    float acc[8][4];
#pragma unroll
    for (int r = 0; r < 8; r++)
#pragma unroll
        for (int c = 0; c < 4; c++) acc[r][c] = 0.f;

    int lr = lane >> 2;           // which of my warp's 8 rows this lane stages
    int lv = lane & 3;            // float4 slot within the 32-k row tile
    int row_l = rowBase + lr;
    float inv = (row_l < n) ? invdeg[row_l] : 0.f;

    for (int kt = 0; kt < 4; kt++) {
        __syncthreads();
        // W tiles: 32x128 each, contiguous; 1024 float4 each, 4 per thread
        const float4* wl4 = (const float4*)(Wl + kt * 32 * F);
        const float4* wr4 = (const float4*)(Wr + kt * 32 * F);
        float4* sl4 = (float4*)&sWl[0][0];
        float4* sr4 = (float4*)&sWr[0][0];
#pragma unroll
        for (int i = 0; i < 4; i++) {
            sl4[tid + 256 * i] = wl4[tid + 256 * i];
            sr4[tid + 256 * i] = wr4[tid + 256 * i];
        }
        // row tiles: per warp 8 rows x 32 k values of agg (scaled) and root
#pragma unroll
        for (int h = 0; h < 2; h++) {
            int v = lv + 4 * h;
            float4 a, xv;
            if (row_l < n) {
                a  = ((const float4*)(agg  + (long)row_l * F + kt * 32))[v];
                xv = ((const float4*)(root + (long)row_l * F + kt * 32))[v];
                a.x *= inv; a.y *= inv; a.z *= inv; a.w *= inv;
            } else {
                a = xv = make_float4(0.f, 0.f, 0.f, 0.f);
            }
            ((float4*)&rta[w][lr][0])[v] = a;
            ((float4*)&rtx[w][lr][0])[v] = xv;
        }
        __syncthreads();
#pragma unroll
        for (int k = 0; k < 32; k++) {
            float4 wl = ((const float4*)&sWl[k][0])[lane];
            float4 wr = ((const float4*)&sWr[k][0])[lane];
#pragma unroll
            for (int r = 0; r < 8; r++) {
                float a  = rta[w][r][k];
                float xv = rtx[w][r][k];
                acc[r][0] = fmaf(a, wl.x, acc[r][0]);
                acc[r][1] = fmaf(a, wl.y, acc[r][1]);
                acc[r][2] = fmaf(a, wl.z, acc[r][2]);
                acc[r][3] = fmaf(a, wl.w, acc[r][3]);
                acc[r][0] = fmaf(xv, wr.x, acc[r][0]);
                acc[r][1] = fmaf(xv, wr.y, acc[r][1]);
                acc[r][2] = fmaf(xv, wr.z, acc[r][2]);
                acc[r][3] = fmaf(xv, wr.w, acc[r][3]);
            }
        }
    }

    float4 bv = ((const float4*)bias)[lane];
#pragma unroll
    for (int r = 0; r < 8; r++) {
        int row = rowBase + r;
        if (row < n) {
            float4 o;
            o.x = fmaxf(acc[r][0] + bv.x, 0.f);
            o.y = fmaxf(acc[r][1] + bv.y, 0.f);
            o.z = fmaxf(acc[r][2] + bv.z, 0.f);
            o.w = fmaxf(acc[r][3] + bv.w, 0.f);
            ((float4*)(out + (long)row * F))[lane] = o;
        }
    }
}

// ---------------- final FC: out = h @ Wfc + bfc  (128 -> 2) ------------------
__global__ __launch_bounds__(128) void fc_kernel(
    const float* __restrict__ h, const float* __restrict__ Wfc,
    const float* __restrict__ bfc, float* __restrict__ out, int n)
{
    __shared__ float sw[F * 2];
    for (int j = threadIdx.x; j < F * 2; j += blockDim.x) sw[j] = Wfc[j];
    __syncthreads();
    int i = blockIdx.x * blockDim.x + threadIdx.x;
    if (i >= n) return;
    float a0 = bfc[0], a1 = bfc[1];
    const float4* hp = (const float4*)(h + (long)i * F);
#pragma unroll
    for (int k4 = 0; k4 < 32; k4++) {
        float4 v = hp[k4];
        int k = k4 * 4;
        a0 = fmaf(v.x, sw[(k + 0) * 2 + 0], a0);
        a1 = fmaf(v.x, sw[(k + 0) * 2 + 1], a1);
        a0 = fmaf(v.y, sw[(k + 1) * 2 + 0], a0);
        a1 = fmaf(v.y, sw[(k + 1) * 2 + 1], a1);
        a0 = fmaf(v.z, sw[(k + 2) * 2 + 0], a0);
        a1 = fmaf(v.z, sw[(k + 2) * 2 + 1], a1);
        a0 = fmaf(v.w, sw[(k + 3) * 2 + 0], a0);
        a1 = fmaf(v.w, sw[(k + 3) * 2 + 1], a1);
    }
    float2 o; o.x = a0; o.y = a1;
    ((float2*)out)[i] = o;
}

// -----------------------------------------------------------------------------
extern "C" void kernel_launch(void* const* d_in, const int* in_sizes, int n_in,
                              void* d_out, int out_size)
{
    const float* x    = (const float*)d_in[0];
    const void*  ei   = d_in[1];                 // int32 or int64, auto-detected
    const float* W1l  = (const float*)d_in[2];
    const float* W1r  = (const float*)d_in[3];
    const float* b1   = (const float*)d_in[4];
    const float* W2l  = (const float*)d_in[5];
    const float* W2r  = (const float*)d_in[6];
    const float* b2   = (const float*)d_in[7];
    const float* Wfc  = (const float*)d_in[8];
    const float* bfc  = (const float*)d_in[9];
    float*       out  = (float*)d_out;

    int n  = in_sizes[0] / F;       // 50000
    int nE = in_sizes[1] / 2;       // 800000

    float *deg, *agg, *h1, *h2;
    cudaGetSymbolAddress((void**)&deg, g_deg);
    cudaGetSymbolAddress((void**)&agg, g_agg);
    cudaGetSymbolAddress((void**)&h1,  g_h1);
    cudaGetSymbolAddress((void**)&h2,  g_h2);

    int aggN4 = n * F / 4;
    int degN4 = (n + 3) / 4;

    detect_kernel<<<1, 256>>>((const int*)ei);

    // ---- layer 1 ----
    zero_kernel<<<512, 256>>>(agg, aggN4);
    zero_kernel<<<64, 256>>>(deg, degN4);
    deg_kernel<<<(nE + 255) / 256, 256>>>(ei, deg, nE);
    scatter_kernel<<<(nE + 7) / 8, 256>>>(ei, x, agg, nE);
    invdeg_kernel<<<(n + 255) / 256, 256>>>(deg, n);
    sage_gemm_kernel<<<(n + 63) / 64, 256>>>(agg, x, deg, W1l, W1r, b1, h1, n);

    // ---- layer 2 ----
    zero_kernel<<<512, 256>>>(agg, aggN4);
    scatter_kernel<<<(nE + 7) / 8, 256>>>(ei, h1, agg, nE);
    sage_gemm_kernel<<<(n + 63) / 64, 256>>>(agg, h1, deg, W2l, W2r, b2, h2, n);

    // ---- FC head ----
    fc_kernel<<<(n + 127) / 128, 128>>>(h2, Wfc, bfc, out, n);
}

// round 5
// speedup vs baseline: 1.2565x; 1.2565x over previous
#include <cuda_runtime.h>
#include <cuda_bf16.h>

#define NODES 50000
#define NEDGES 800000
#define F 128

// ---------------- scratch (device globals; no runtime allocation) ------------
__device__ int   g_cnt[NODES];          // in-degree counts
__device__ int   g_off[NODES + 1];      // CSR row offsets (by dst)
__device__ int   g_cur[NODES];          // fill cursors
__device__ int   g_csr[NEDGES];         // CSR column ids (src of each edge)
__device__ float g_agg[NODES * F];      // mean-aggregated features
__device__ float g_h1[NODES * F];
__device__ float g_h2[NODES * F];
__device__ int   g_is64;                // 1 if edge_index is int64, 0 if int32

// ---------------- index dtype detection --------------------------------------
// int64 little-endian with values < 50000 => every odd 32-bit word is 0.
__global__ void detect_kernel(const int* __restrict__ p) {
    __shared__ int ok;
    if (threadIdx.x == 0) ok = 1;
    __syncthreads();
    if (p[2 * threadIdx.x + 1] != 0) atomicAnd(&ok, 0);
    __syncthreads();
    if (threadIdx.x == 0) g_is64 = ok;
}

__device__ __forceinline__ int load_idx(const void* __restrict__ p, long i, int is64) {
    if (is64) return (int)((const long long*)p)[i];
    return ((const int*)p)[i];
}

// ---------------- zero fill --------------------------------------------------
__global__ void zero_kernel(int* __restrict__ p, int n4) {
    int i = blockIdx.x * blockDim.x + threadIdx.x;
    int4 z = make_int4(0, 0, 0, 0);
    for (; i < n4; i += gridDim.x * blockDim.x)
        ((int4*)p)[i] = z;
}

// ---------------- CSR build --------------------------------------------------
__global__ void count_kernel(const void* __restrict__ ei, int* __restrict__ cnt, int nE) {
    int i = blockIdx.x * blockDim.x + threadIdx.x;
    int is64 = g_is64;
    if (i < nE) {
        int d = load_idx(ei, (long)nE + i, is64);
        if ((unsigned)d < NODES) atomicAdd(&cnt[d], 1);
    }
}

// single-block exclusive scan of 50000 counts (1024 threads, ~49 elems each)
__global__ __launch_bounds__(1024) void scan_kernel(
    const int* __restrict__ cnt, int* __restrict__ off, int n)
{
    __shared__ int part[1024];
    int tid = threadIdx.x;
    int chunk = (n + 1023) / 1024;
    int base = tid * chunk;
    int sum = 0;
    for (int i = 0; i < chunk; i++) {
        int j = base + i;
        if (j < n) sum += cnt[j];
    }
    part[tid] = sum;
    __syncthreads();
    // Hillis-Steele inclusive scan
    for (int d = 1; d < 1024; d <<= 1) {
        int t = (tid >= d) ? part[tid - d] : 0;
        __syncthreads();
        part[tid] += t;
        __syncthreads();
    }
    int running = part[tid] - sum;   // exclusive prefix
    for (int i = 0; i < chunk; i++) {
        int j = base + i;
        if (j < n) { off[j] = running; running += cnt[j]; }
    }
    if (tid == 1023) off[n] = part[1023];
}

__global__ void fill_kernel(const void* __restrict__ ei,
                            const int* __restrict__ off, int* __restrict__ cur,
                            int* __restrict__ csr, int nE)
{
    int i = blockIdx.x * blockDim.x + threadIdx.x;
    int is64 = g_is64;
    if (i < nE) {
        int s = load_idx(ei, i, is64);
        int d = load_idx(ei, (long)nE + i, is64);
        if ((unsigned)s < NODES && (unsigned)d < NODES) {
            int pos = off[d] + atomicAdd(&cur[d], 1);
            csr[pos] = s;
        }
    }
}

// ---------------- gather-aggregate: agg[i] = mean_{j in N(i)} feat[j] --------
// one warp per node, lane covers one float4 (32 x float4 = 128 floats)
__global__ __launch_bounds__(256) void gather_kernel(
    const int* __restrict__ off, const int* __restrict__ csr,
    const float* __restrict__ feat, float* __restrict__ agg, int n)
{
    int w = (blockIdx.x * blockDim.x + threadIdx.x) >> 5;
    int lane = threadIdx.x & 31;
    if (w >= n) return;
    int o0 = off[w], o1 = off[w + 1];
    float4 a0 = make_float4(0.f, 0.f, 0.f, 0.f);
    float4 a1 = make_float4(0.f, 0.f, 0.f, 0.f);
    int e = o0;
    for (; e + 1 < o1; e += 2) {
        int s0 = __ldg(&csr[e]);
        int s1 = __ldg(&csr[e + 1]);
        float4 v0 = ((const float4*)(feat + (long)s0 * F))[lane];
        float4 v1 = ((const float4*)(feat + (long)s1 * F))[lane];
        a0.x += v0.x; a0.y += v0.y; a0.z += v0.z; a0.w += v0.w;
        a1.x += v1.x; a1.y += v1.y; a1.z += v1.z; a1.w += v1.w;
    }
    if (e < o1) {
        int s0 = __ldg(&csr[e]);
        float4 v0 = ((const float4*)(feat + (long)s0 * F))[lane];
        a0.x += v0.x; a0.y += v0.y; a0.z += v0.z; a0.w += v0.w;
    }
    float inv = 1.0f / fmaxf((float)(o1 - o0), 1.0f);
    float4 o;
    o.x = (a0.x + a1.x) * inv;
    o.y = (a0.y + a1.y) * inv;
    o.z = (a0.z + a1.z) * inv;
    o.w = (a0.w + a1.w) * inv;
    ((float4*)(agg + (long)w * F))[lane] = o;
}

// ---------------- fused SAGE layer: out = relu(agg @ Wl + root @ Wr + b) -----
// block: 256 thr (8 warps), 64 rows/block (8 rows/warp), lane covers 4 cols.
__global__ __launch_bounds__(256) void sage_gemm_kernel(
    const float* __restrict__ agg, const float* __restrict__ root,
    const float* __restrict__ Wl, const float* __restrict__ Wr,
    const float* __restrict__ bias, float* __restrict__ out, int n)
{
    __shared__ float sWl[32][F];
    __shared__ float sWr[32][F];
    __shared__ float rta[8][8][32];
    __shared__ float rtx[8][8][32];

    int tid  = threadIdx.x;
    int w    = tid >> 5;
    int lane = tid & 31;
    int rowBase = blockIdx.x * 64 + w * 8;

    float acc[8][4];
#pragma unroll
    for (int r = 0; r < 8; r++)
#pragma unroll
        for (int c = 0; c < 4; c++) acc[r][c] = 0.f;

    int lr = lane >> 2;
    int lv = lane & 3;
    int row_l = rowBase + lr;

    for (int kt = 0; kt < 4; kt++) {
        __syncthreads();
        const float4* wl4 = (const float4*)(Wl + kt * 32 * F);
        const float4* wr4 = (const float4*)(Wr + kt * 32 * F);
        float4* sl4 = (float4*)&sWl[0][0];
        float4* sr4 = (float4*)&sWr[0][0];
#pragma unroll
        for (int i = 0; i < 4; i++) {
            sl4[tid + 256 * i] = wl4[tid + 256 * i];
            sr4[tid + 256 * i] = wr4[tid + 256 * i];
        }
#pragma unroll
        for (int h = 0; h < 2; h++) {
            int v = lv + 4 * h;
            float4 a, xv;
            if (row_l < n) {
                a  = ((const float4*)(agg  + (long)row_l * F + kt * 32))[v];
                xv = ((const float4*)(root + (long)row_l * F + kt * 32))[v];
            } else {
                a = xv = make_float4(0.f, 0.f, 0.f, 0.f);
            }
            ((float4*)&rta[w][lr][0])[v] = a;
            ((float4*)&rtx[w][lr][0])[v] = xv;
        }
        __syncthreads();
#pragma unroll
        for (int k = 0; k < 32; k++) {
            float4 wl = ((const float4*)&sWl[k][0])[lane];
            float4 wr = ((const float4*)&sWr[k][0])[lane];
#pragma unroll
            for (int r = 0; r < 8; r++) {
                float a  = rta[w][r][k];
                float xv = rtx[w][r][k];
                acc[r][0] = fmaf(a, wl.x, acc[r][0]);
                acc[r][1] = fmaf(a, wl.y, acc[r][1]);
                acc[r][2] = fmaf(a, wl.z, acc[r][2]);
                acc[r][3] = fmaf(a, wl.w, acc[r][3]);
                acc[r][0] = fmaf(xv, wr.x, acc[r][0]);
                acc[r][1] = fmaf(xv, wr.y, acc[r][1]);
                acc[r][2] = fmaf(xv, wr.z, acc[r][2]);
                acc[r][3] = fmaf(xv, wr.w, acc[r][3]);
            }
        }
    }

    float4 bv = ((const float4*)bias)[lane];
#pragma unroll
    for (int r = 0; r < 8; r++) {
        int row = rowBase + r;
        if (row < n) {
            float4 o;
            o.x = fmaxf(acc[r][0] + bv.x, 0.f);
            o.y = fmaxf(acc[r][1] + bv.y, 0.f);
            o.z = fmaxf(acc[r][2] + bv.z, 0.f);
            o.w = fmaxf(acc[r][3] + bv.w, 0.f);
            ((float4*)(out + (long)row * F))[lane] = o;
        }
    }
}

// ---------------- final FC: out = h @ Wfc + bfc  (128 -> 2) ------------------
__global__ __launch_bounds__(128) void fc_kernel(
    const float* __restrict__ h, const float* __restrict__ Wfc,
    const float* __restrict__ bfc, float* __restrict__ out, int n)
{
    __shared__ float sw[F * 2];
    for (int j = threadIdx.x; j < F * 2; j += blockDim.x) sw[j] = Wfc[j];
    __syncthreads();
    int i = blockIdx.x * blockDim.x + threadIdx.x;
    if (i >= n) return;
    float a0 = bfc[0], a1 = bfc[1];
    const float4* hp = (const float4*)(h + (long)i * F);
#pragma unroll
    for (int k4 = 0; k4 < 32; k4++) {
        float4 v = hp[k4];
        int k = k4 * 4;
        a0 = fmaf(v.x, sw[(k + 0) * 2 + 0], a0);
        a1 = fmaf(v.x, sw[(k + 0) * 2 + 1], a1);
        a0 = fmaf(v.y, sw[(k + 1) * 2 + 0], a0);
        a1 = fmaf(v.y, sw[(k + 1) * 2 + 1], a1);
        a0 = fmaf(v.z, sw[(k + 2) * 2 + 0], a0);
        a1 = fmaf(v.z, sw[(k + 2) * 2 + 1], a1);
        a0 = fmaf(v.w, sw[(k + 3) * 2 + 0], a0);
        a1 = fmaf(v.w, sw[(k + 3) * 2 + 1], a1);
    }
    float2 o; o.x = a0; o.y = a1;
    ((float2*)out)[i] = o;
}

// -----------------------------------------------------------------------------
extern "C" void kernel_launch(void* const* d_in, const int* in_sizes, int n_in,
                              void* d_out, int out_size)
{
    const float* x    = (const float*)d_in[0];
    const void*  ei   = d_in[1];                 // int32 or int64, auto-detected
    const float* W1l  = (const float*)d_in[2];
    const float* W1r  = (const float*)d_in[3];
    const float* b1   = (const float*)d_in[4];
    const float* W2l  = (const float*)d_in[5];
    const float* W2r  = (const float*)d_in[6];
    const float* b2   = (const float*)d_in[7];
    const float* Wfc  = (const float*)d_in[8];
    const float* bfc  = (const float*)d_in[9];
    float*       out  = (float*)d_out;

    int n  = in_sizes[0] / F;       // 50000
    int nE = in_sizes[1] / 2;       // 800000

    int *cnt, *off, *cur, *csr;
    float *agg, *h1, *h2;
    cudaGetSymbolAddress((void**)&cnt, g_cnt);
    cudaGetSymbolAddress((void**)&off, g_off);
    cudaGetSymbolAddress((void**)&cur, g_cur);
    cudaGetSymbolAddress((void**)&csr, g_csr);
    cudaGetSymbolAddress((void**)&agg, g_agg);
    cudaGetSymbolAddress((void**)&h1,  g_h1);
    cudaGetSymbolAddress((void**)&h2,  g_h2);

    detect_kernel<<<1, 256>>>((const int*)ei);

    // ---- CSR build (once, reused for both layers) ----
    zero_kernel<<<32, 256>>>(cnt, (n + 3) / 4);
    zero_kernel<<<32, 256>>>(cur, (n + 3) / 4);
    count_kernel<<<(nE + 255) / 256, 256>>>(ei, cnt, nE);
    scan_kernel<<<1, 1024>>>(cnt, off, n);
    fill_kernel<<<(nE + 255) / 256, 256>>>(ei, off, cur, csr, nE);

    int gatherBlocks = (n * 32 + 255) / 256;

    // ---- layer 1 ----
    gather_kernel<<<gatherBlocks, 256>>>(off, csr, x, agg, n);
    sage_gemm_kernel<<<(n + 63) / 64, 256>>>(agg, x, W1l, W1r, b1, h1, n);

    // ---- layer 2 ----
    gather_kernel<<<gatherBlocks, 256>>>(off, csr, h1, agg, n);
    sage_gemm_kernel<<<(n + 63) / 64, 256>>>(agg, h1, W2l, W2r, b2, h2, n);

    // ---- FC head ----
    fc_kernel<<<(n + 127) / 128, 128>>>(h2, Wfc, bfc, out, n);
}

// round 6
// speedup vs baseline: 1.2922x; 1.0284x over previous
#include <cuda_runtime.h>

#define NODES 50000
#define NEDGES 800000
#define F 128

// ---------------- scratch (device globals; no runtime allocation) ------------
__device__ int   g_cnt[NODES];
__device__ int   g_off[NODES + 1];
__device__ int   g_cur[NODES];
__device__ int   g_csr[NEDGES];
__device__ float g_h1[NODES * F];
__device__ int   g_is64;

// ---------------- index dtype detection --------------------------------------
__global__ void detect_kernel(const int* __restrict__ p) {
    __shared__ int ok;
    if (threadIdx.x == 0) ok = 1;
    __syncthreads();
    if (p[2 * threadIdx.x + 1] != 0) atomicAnd(&ok, 0);
    __syncthreads();
    if (threadIdx.x == 0) g_is64 = ok;
}

__device__ __forceinline__ int load_idx(const void* __restrict__ p, long i, int is64) {
    if (is64) return (int)((const long long*)p)[i];
    return ((const int*)p)[i];
}

// ---------------- zero fill (two arrays in one launch) ------------------------
__global__ void zero2_kernel(int* __restrict__ a, int* __restrict__ b, int n4) {
    int i = blockIdx.x * blockDim.x + threadIdx.x;
    int4 z = make_int4(0, 0, 0, 0);
    for (; i < n4; i += gridDim.x * blockDim.x) {
        ((int4*)a)[i] = z;
        ((int4*)b)[i] = z;
    }
}

// ---------------- CSR build --------------------------------------------------
__global__ void count_kernel(const void* __restrict__ ei, int* __restrict__ cnt, int nE) {
    int i = blockIdx.x * blockDim.x + threadIdx.x;
    int is64 = g_is64;
    if (i < nE) {
        int d = load_idx(ei, (long)nE + i, is64);
        if ((unsigned)d < NODES) atomicAdd(&cnt[d], 1);
    }
}

__global__ __launch_bounds__(1024) void scan_kernel(
    const int* __restrict__ cnt, int* __restrict__ off, int n)
{
    __shared__ int part[1024];
    int tid = threadIdx.x;
    int chunk = (n + 1023) / 1024;
    int base = tid * chunk;
    int sum = 0;
    for (int i = 0; i < chunk; i++) {
        int j = base + i;
        if (j < n) sum += cnt[j];
    }
    part[tid] = sum;
    __syncthreads();
    for (int d = 1; d < 1024; d <<= 1) {
        int t = (tid >= d) ? part[tid - d] : 0;
        __syncthreads();
        part[tid] += t;
        __syncthreads();
    }
    int running = part[tid] - sum;
    for (int i = 0; i < chunk; i++) {
        int j = base + i;
        if (j < n) { off[j] = running; running += cnt[j]; }
    }
    if (tid == 1023) off[n] = part[1023];
}

__global__ void fill_kernel(const void* __restrict__ ei,
                            const int* __restrict__ off, int* __restrict__ cur,
                            int* __restrict__ csr, int nE)
{
    int i = blockIdx.x * blockDim.x + threadIdx.x;
    int is64 = g_is64;
    if (i < nE) {
        int s = load_idx(ei, i, is64);
        int d = load_idx(ei, (long)nE + i, is64);
        if ((unsigned)s < NODES && (unsigned)d < NODES) {
            int pos = off[d] + atomicAdd(&cur[d], 1);
            csr[pos] = s;
        }
    }
}

// ---------------- fused SAGE layer -------------------------------------------
// out = relu( mean_{j in N(i)} feat[j] @ Wl + feat[i] @ Wr + b )      (FUSE_FC=0)
// out = (the above) @ Wfc + bfc  fused into epilogue                  (FUSE_FC=1)
//
// block: 256 thr (8 warps), 64 rows/block. Phase A: gather neighbor means +
// root rows into smem. Phase B: dual-GEMM with packed f32x2 FMA (FFMA2).
template <int FUSE_FC>
__global__ __launch_bounds__(256) void sage_layer_kernel(
    const int* __restrict__ off, const int* __restrict__ csr,
    const float* __restrict__ feat,
    const float* __restrict__ Wl, const float* __restrict__ Wr,
    const float* __restrict__ bias,
    const float* __restrict__ Wfc, const float* __restrict__ bfc,
    float* __restrict__ out, int n)
{
    extern __shared__ float smem[];
    float* sAgg  = smem;                    // [64][128]
    float* sRoot = smem + 64 * F;           // [64][128]
    float* sWl   = smem + 2 * 64 * F;       // [32][128]
    float* sWr   = sWl + 32 * F;            // [32][128]
    float* sFc   = sWr + 32 * F;            // [256] (only used when FUSE_FC)

    int tid  = threadIdx.x;
    int w    = tid >> 5;
    int lane = tid & 31;
    int rowBase = blockIdx.x * 64;

    // ---------- Phase A: gather (warp w handles rows w*8 .. w*8+7) ----------
    for (int r = 0; r < 8; r++) {
        int rl = w * 8 + r;
        int row = rowBase + rl;
        float4 a0 = make_float4(0.f, 0.f, 0.f, 0.f);
        float4 a1 = make_float4(0.f, 0.f, 0.f, 0.f);
        float4 a2 = make_float4(0.f, 0.f, 0.f, 0.f);
        float4 a3 = make_float4(0.f, 0.f, 0.f, 0.f);
        float inv = 0.f;
        if (row < n) {
            int o0 = __ldg(&off[row]), o1 = __ldg(&off[row + 1]);
            int e = o0;
            for (; e + 3 < o1; e += 4) {
                int i0 = __ldg(&csr[e]);
                int i1 = __ldg(&csr[e + 1]);
                int i2 = __ldg(&csr[e + 2]);
                int i3 = __ldg(&csr[e + 3]);
                float4 v0 = ((const float4*)(feat + (long)i0 * F))[lane];
                float4 v1 = ((const float4*)(feat + (long)i1 * F))[lane];
                float4 v2 = ((const float4*)(feat + (long)i2 * F))[lane];
                float4 v3 = ((const float4*)(feat + (long)i3 * F))[lane];
                a0.x += v0.x; a0.y += v0.y; a0.z += v0.z; a0.w += v0.w;
                a1.x += v1.x; a1.y += v1.y; a1.z += v1.z; a1.w += v1.w;
                a2.x += v2.x; a2.y += v2.y; a2.z += v2.z; a2.w += v2.w;
                a3.x += v3.x; a3.y += v3.y; a3.z += v3.z; a3.w += v3.w;
            }
            for (; e < o1; e++) {
                int i0 = __ldg(&csr[e]);
                float4 v0 = ((const float4*)(feat + (long)i0 * F))[lane];
                a0.x += v0.x; a0.y += v0.y; a0.z += v0.z; a0.w += v0.w;
            }
            inv = 1.0f / fmaxf((float)(o1 - o0), 1.0f);
        }
        float4 o;
        o.x = (a0.x + a1.x + a2.x + a3.x) * inv;
        o.y = (a0.y + a1.y + a2.y + a3.y) * inv;
        o.z = (a0.z + a1.z + a2.z + a3.z) * inv;
        o.w = (a0.w + a1.w + a2.w + a3.w) * inv;
        ((float4*)&sAgg[rl * F])[lane] = o;
    }
    // root rows: 64 rows x 32 float4 = 2048 float4, 8 per thread
#pragma unroll
    for (int i = 0; i < 8; i++) {
        int idx = tid + 256 * i;
        int row = rowBase + (idx >> 5);
        int c = idx & 31;
        float4 v = make_float4(0.f, 0.f, 0.f, 0.f);
        if (row < n) v = ((const float4*)(feat + (long)row * F))[c];
        ((float4*)sRoot)[idx] = v;
    }
    if (FUSE_FC) {
        sFc[tid] = Wfc[tid];   // 128x2 = 256 floats, exactly one per thread
    }

    // ---------- Phase B: dual-GEMM with FFMA2 --------------------------------
    unsigned long long acc01[8], acc23[8];
#pragma unroll
    for (int r = 0; r < 8; r++) { acc01[r] = 0ull; acc23[r] = 0ull; }

    for (int kt = 0; kt < 4; kt++) {
        __syncthreads();
        const float4* wl4 = (const float4*)(Wl + kt * 32 * F);
        const float4* wr4 = (const float4*)(Wr + kt * 32 * F);
#pragma unroll
        for (int i = 0; i < 4; i++) {
            ((float4*)sWl)[tid + 256 * i] = wl4[tid + 256 * i];
            ((float4*)sWr)[tid + 256 * i] = wr4[tid + 256 * i];
        }
        __syncthreads();
#pragma unroll
        for (int k = 0; k < 32; k++) {
            ulonglong2 wl = ((const ulonglong2*)(sWl + k * F))[lane];
            ulonglong2 wr = ((const ulonglong2*)(sWr + k * F))[lane];
#pragma unroll
            for (int r = 0; r < 8; r++) {
                int rl = w * 8 + r;
                unsigned ai = __float_as_uint(sAgg[rl * F + kt * 32 + k]);
                unsigned xi = __float_as_uint(sRoot[rl * F + kt * 32 + k]);
                unsigned long long a2, x2;
                asm("mov.b64 %0, {%1, %1};" : "=l"(a2) : "r"(ai));
                asm("mov.b64 %0, {%1, %1};" : "=l"(x2) : "r"(xi));
                asm("fma.rn.f32x2 %0, %1, %2, %0;" : "+l"(acc01[r]) : "l"(a2), "l"(wl.x));
                asm("fma.rn.f32x2 %0, %1, %2, %0;" : "+l"(acc23[r]) : "l"(a2), "l"(wl.y));
                asm("fma.rn.f32x2 %0, %1, %2, %0;" : "+l"(acc01[r]) : "l"(x2), "l"(wr.x));
                asm("fma.rn.f32x2 %0, %1, %2, %0;" : "+l"(acc23[r]) : "l"(x2), "l"(wr.y));
            }
        }
    }

    // ---------- epilogue -----------------------------------------------------
    float4 bv = ((const float4*)bias)[lane];
#pragma unroll
    for (int r = 0; r < 8; r++) {
        int row = rowBase + w * 8 + r;
        unsigned u0, u1, u2, u3;
        asm("mov.b64 {%0, %1}, %2;" : "=r"(u0), "=r"(u1) : "l"(acc01[r]));
        asm("mov.b64 {%0, %1}, %2;" : "=r"(u2), "=r"(u3) : "l"(acc23[r]));
        float h0 = fmaxf(__uint_as_float(u0) + bv.x, 0.f);
        float h1 = fmaxf(__uint_as_float(u1) + bv.y, 0.f);
        float h2 = fmaxf(__uint_as_float(u2) + bv.z, 0.f);
        float h3 = fmaxf(__uint_as_float(u3) + bv.w, 0.f);
        if (!FUSE_FC) {
            if (row < n) {
                float4 o; o.x = h0; o.y = h1; o.z = h2; o.w = h3;
                ((float4*)(out + (long)row * F))[lane] = o;
            }
        } else {
            int c0 = lane * 4;
            float p0 = h0 * sFc[(c0 + 0) * 2 + 0] + h1 * sFc[(c0 + 1) * 2 + 0]
                     + h2 * sFc[(c0 + 2) * 2 + 0] + h3 * sFc[(c0 + 3) * 2 + 0];
            float p1 = h0 * sFc[(c0 + 0) * 2 + 1] + h1 * sFc[(c0 + 1) * 2 + 1]
                     + h2 * sFc[(c0 + 2) * 2 + 1] + h3 * sFc[(c0 + 3) * 2 + 1];
#pragma unroll
            for (int d = 16; d > 0; d >>= 1) {
                p0 += __shfl_xor_sync(0xFFFFFFFFu, p0, d);
                p1 += __shfl_xor_sync(0xFFFFFFFFu, p1, d);
            }
            if (lane == 0 && row < n) {
                float2 o;
                o.x = p0 + __ldg(&bfc[0]);
                o.y = p1 + __ldg(&bfc[1]);
                ((float2*)out)[row] = o;
            }
        }
    }
}

// -----------------------------------------------------------------------------
extern "C" void kernel_launch(void* const* d_in, const int* in_sizes, int n_in,
                              void* d_out, int out_size)
{
    const float* x    = (const float*)d_in[0];
    const void*  ei   = d_in[1];                 // int32 or int64, auto-detected
    const float* W1l  = (const float*)d_in[2];
    const float* W1r  = (const float*)d_in[3];
    const float* b1   = (const float*)d_in[4];
    const float* W2l  = (const float*)d_in[5];
    const float* W2r  = (const float*)d_in[6];
    const float* b2   = (const float*)d_in[7];
    const float* Wfc  = (const float*)d_in[8];
    const float* bfc  = (const float*)d_in[9];
    float*       out  = (float*)d_out;

    int n  = in_sizes[0] / F;       // 50000
    int nE = in_sizes[1] / 2;       // 800000

    int *cnt, *off, *cur, *csr;
    float *h1;
    cudaGetSymbolAddress((void**)&cnt, g_cnt);
    cudaGetSymbolAddress((void**)&off, g_off);
    cudaGetSymbolAddress((void**)&cur, g_cur);
    cudaGetSymbolAddress((void**)&csr, g_csr);
    cudaGetSymbolAddress((void**)&h1,  g_h1);

    const int SMEM = (64 * F * 2 + 32 * F * 2 + 256) * 4;   // 99,328 bytes
    cudaFuncSetAttribute(sage_layer_kernel<0>,
                         cudaFuncAttributeMaxDynamicSharedMemorySize, SMEM);
    cudaFuncSetAttribute(sage_layer_kernel<1>,
                         cudaFuncAttributeMaxDynamicSharedMemorySize, SMEM);

    detect_kernel<<<1, 256>>>((const int*)ei);

    // ---- CSR build (once, reused for both layers) ----
    zero2_kernel<<<32, 256>>>(cnt, cur, (n + 3) / 4);
    count_kernel<<<(nE + 255) / 256, 256>>>(ei, cnt, nE);
    scan_kernel<<<1, 1024>>>(cnt, off, n);
    fill_kernel<<<(nE + 255) / 256, 256>>>(ei, off, cur, csr, nE);

    int blocks = (n + 63) / 64;

    // ---- layer 1 (writes h1) ----
    sage_layer_kernel<0><<<blocks, 256, SMEM>>>(
        off, csr, x, W1l, W1r, b1, (const float*)0, (const float*)0, h1, n);

    // ---- layer 2 + FC head fused (writes logits) ----
    sage_layer_kernel<1><<<blocks, 256, SMEM>>>(
        off, csr, h1, W2l, W2r, b2, Wfc, bfc, out, n);
}